// round 3
// baseline (speedup 1.0000x reference)
#include <cuda_runtime.h>
#include <cuda_bf16.h>

// Grid shape fixed for this problem instance.
#define GH 704
#define GW 704
#define GD 64
#define PTS_PER_THREAD 4
#define BLOCK 256

__device__ float g_sum;          // zero-init at module load; reset by last block each launch
__device__ unsigned g_count;     // ditto

__device__ __forceinline__ float read_grid_factor(const void* p) {
    // grid_factor may be stored as int32 (10) or float32 (10.0f).
    int bits = *(const int*)p;
    if (bits > 0 && bits < 1000000) return (float)bits;   // small-int bit pattern
    return __int_as_float(bits);
}

__device__ __forceinline__ float trilerp(const float* __restrict__ grid,
                                         float px, float py, float pz,
                                         float gx, float gy, float gz, float gf)
{
    float sx = fminf(fmaxf((px - gx) * gf, 0.0f), (float)(GH - 1));
    float sy = fminf(fmaxf((py - gy) * gf, 0.0f), (float)(GW - 1));
    float sz = fminf(fmaxf((pz - gz) * gf, 0.0f), (float)(GD - 1));

    int x0 = (int)floorf(sx); int x1 = min(x0 + 1, GH - 1);
    int y0 = (int)floorf(sy); int y1 = min(y0 + 1, GW - 1);
    int z0 = (int)floorf(sz); int z1 = min(z0 + 1, GD - 1);

    float wx = sx - (float)x0;
    float wy = sy - (float)y0;
    float wz = sz - (float)z0;

    long b00 = ((long)x0 * GW + y0) * GD;
    long b01 = ((long)x0 * GW + y1) * GD;
    long b10 = ((long)x1 * GW + y0) * GD;
    long b11 = ((long)x1 * GW + y1) * GD;

    float c000 = __ldg(&grid[b00 + z0]);
    float c001 = __ldg(&grid[b00 + z1]);
    float c010 = __ldg(&grid[b01 + z0]);
    float c011 = __ldg(&grid[b01 + z1]);
    float c100 = __ldg(&grid[b10 + z0]);
    float c101 = __ldg(&grid[b10 + z1]);
    float c110 = __ldg(&grid[b11 + z0]);
    float c111 = __ldg(&grid[b11 + z1]);

    float c00 = c000 + (c001 - c000) * wz;
    float c01 = c010 + (c011 - c010) * wz;
    float c10 = c100 + (c101 - c100) * wz;
    float c11 = c110 + (c111 - c110) * wz;
    float c0  = c00  + (c01  - c00 ) * wy;
    float c1  = c10  + (c11  - c10 ) * wy;
    return c0 + (c1 - c0) * wx;
}

__global__ __launch_bounds__(BLOCK)
void dt_loss_kernel(const float* __restrict__ pc1,
                    const float* __restrict__ flow,
                    const float* __restrict__ grid,
                    const float* __restrict__ gmin,
                    const void*  __restrict__ gfac,
                    float* __restrict__ out,
                    int N, int off)
{
    const float gf = read_grid_factor(gfac);
    const float gx = __ldg(&gmin[0]);
    const float gy = __ldg(&gmin[1]);
    const float gz = __ldg(&gmin[2]);

    int t    = blockIdx.x * BLOCK + threadIdx.x;
    int base = t * PTS_PER_THREAD;

    float acc = 0.0f;

    if (base + PTS_PER_THREAD <= N) {
        // 3 float4 loads cover 4 points (12 floats). base % 4 == 0 -> 16B aligned.
        const float4* p4 = (const float4*)(pc1  + 3 * (long)base);
        const float4* f4 = (const float4*)(flow + 3 * (long)base);
        float4 pa = p4[0], pb = p4[1], pc_ = p4[2];
        float4 fa = f4[0], fb = f4[1], fc_ = f4[2];

        float px[4], py[4], pz[4];
        px[0] = pa.x + fa.x;  py[0] = pa.y + fa.y;  pz[0] = pa.z + fa.z;
        px[1] = pa.w + fa.w;  py[1] = pb.x + fb.x;  pz[1] = pb.y + fb.y;
        px[2] = pb.z + fb.z;  py[2] = pb.w + fb.w;  pz[2] = pc_.x + fc_.x;
        px[3] = pc_.y + fc_.y; py[3] = pc_.z + fc_.z; pz[3] = pc_.w + fc_.w;

        float v[4];
        #pragma unroll
        for (int k = 0; k < 4; k++)
            v[k] = trilerp(grid, px[k], py[k], pz[k], gx, gy, gz, gf);

        #pragma unroll
        for (int k = 0; k < 4; k++) {
            out[off + base + k] = v[k];
            acc += v[k];
        }
    } else {
        for (int i = base; i < N; i++) {
            float px = pc1[3 * (long)i + 0] + flow[3 * (long)i + 0];
            float py = pc1[3 * (long)i + 1] + flow[3 * (long)i + 1];
            float pz = pc1[3 * (long)i + 2] + flow[3 * (long)i + 2];
            float v = trilerp(grid, px, py, pz, gx, gy, gz, gf);
            out[off + i] = v;
            acc += v;
        }
    }

    // ---- block reduction ----
    __shared__ float warp_sums[BLOCK / 32];
    __shared__ bool  is_last;
    int lane = threadIdx.x & 31;
    int wid  = threadIdx.x >> 5;

    #pragma unroll
    for (int d = 16; d > 0; d >>= 1)
        acc += __shfl_down_sync(0xFFFFFFFFu, acc, d);
    if (lane == 0) warp_sums[wid] = acc;
    __syncthreads();

    if (wid == 0) {
        float s = (lane < BLOCK / 32) ? warp_sums[lane] : 0.0f;
        #pragma unroll
        for (int d = 4; d > 0; d >>= 1)
            s += __shfl_down_sync(0xFFFFFFFFu, s, d);
        if (lane == 0) {
            atomicAdd(&g_sum, s);
            __threadfence();
            unsigned prev = atomicAdd(&g_count, 1u);
            is_last = (prev == gridDim.x - 1);
        }
    }
    __syncthreads();

    // Last block finishes: write mean, reset accumulators for next graph replay.
    if (is_last && threadIdx.x == 0) {
        float total = g_sum;
        if (off > 0) out[0] = total / (float)N;
        g_sum = 0.0f;
        g_count = 0u;
    }
}

extern "C" void kernel_launch(void* const* d_in, const int* in_sizes, int n_in,
                              void* d_out, int out_size)
{
    const float* pc1  = (const float*)d_in[0];
    const float* flow = (const float*)d_in[1];
    const float* grid = (const float*)d_in[2];
    const float* gmin = (const float*)d_in[3];
    const void*  gfac = d_in[4];
    float* out = (float*)d_out;

    int N = in_sizes[0] / 3;
    int off = out_size - N;        // 1 if [mean, dist...], 0 if just [dist...]
    if (off < 0) off = 0;

    int per_block = BLOCK * PTS_PER_THREAD;
    int blocks = (N + per_block - 1) / per_block;

    dt_loss_kernel<<<blocks, BLOCK>>>(pc1, flow, grid, gmin, gfac, out, N, off);
}

// round 4
// speedup vs baseline: 1.2729x; 1.2729x over previous
#include <cuda_runtime.h>
#include <cuda_bf16.h>

// Grid shape fixed for this problem instance.
#define GH 704
#define GW 704
#define GD 64
#define BLOCK 256

__device__ float g_sum;          // zero at load; last block resets each launch
__device__ unsigned g_count;

__device__ __forceinline__ float read_grid_factor(const void* p) {
    // grid_factor may be stored as int32 (10) or float32 (10.0f).
    int bits = *(const int*)p;
    if (bits > 0 && bits < 1000000) return (float)bits;
    return __int_as_float(bits);
}

struct Corner {
    int b00, b01, b10, b11;   // row bases (int: grid < 2^31 elems)
    int z0, z1;
    float wx, wy, wz;
};

__device__ __forceinline__ Corner setup(float px, float py, float pz,
                                        float gx, float gy, float gz, float gf)
{
    Corner c;
    float sx = fminf(fmaxf((px - gx) * gf, 0.0f), (float)(GH - 1));
    float sy = fminf(fmaxf((py - gy) * gf, 0.0f), (float)(GW - 1));
    float sz = fminf(fmaxf((pz - gz) * gf, 0.0f), (float)(GD - 1));

    int x0 = (int)floorf(sx); int x1 = min(x0 + 1, GH - 1);
    int y0 = (int)floorf(sy); int y1 = min(y0 + 1, GW - 1);
    c.z0 = (int)floorf(sz);   c.z1 = min(c.z0 + 1, GD - 1);

    c.wx = sx - (float)x0;
    c.wy = sy - (float)y0;
    c.wz = sz - (float)c.z0;

    c.b00 = (x0 * GW + y0) * GD;
    c.b01 = (x0 * GW + y1) * GD;
    c.b10 = (x1 * GW + y0) * GD;
    c.b11 = (x1 * GW + y1) * GD;
    return c;
}

__device__ __forceinline__ float lerp8(float c000, float c001, float c010, float c011,
                                       float c100, float c101, float c110, float c111,
                                       float wx, float wy, float wz)
{
    float c00 = c000 + (c001 - c000) * wz;
    float c01 = c010 + (c011 - c010) * wz;
    float c10 = c100 + (c101 - c100) * wz;
    float c11 = c110 + (c111 - c110) * wz;
    float c0  = c00  + (c01  - c00 ) * wy;
    float c1  = c10  + (c11  - c10 ) * wy;
    return c0 + (c1 - c0) * wx;
}

__global__ __launch_bounds__(BLOCK)
void dt_loss_kernel(const float* __restrict__ pc1,
                    const float* __restrict__ flow,
                    const float* __restrict__ grid,
                    const float* __restrict__ gmin,
                    const void*  __restrict__ gfac,
                    float* __restrict__ out,
                    int N, int off, int stride)
{
    const float gf = read_grid_factor(gfac);
    const float gx = __ldg(&gmin[0]);
    const float gy = __ldg(&gmin[1]);
    const float gz = __ldg(&gmin[2]);

    int i0 = blockIdx.x * BLOCK + threadIdx.x;
    int i1 = i0 + stride;

    float acc = 0.0f;

    bool has0 = i0 < N;
    bool has1 = i1 < N;

    if (has0 && has1) {
        // Streaming loads (evict-first) — protect grid's L2 residency.
        float p0x = __ldcs(&pc1[3 * i0 + 0]) + __ldcs(&flow[3 * i0 + 0]);
        float p0y = __ldcs(&pc1[3 * i0 + 1]) + __ldcs(&flow[3 * i0 + 1]);
        float p0z = __ldcs(&pc1[3 * i0 + 2]) + __ldcs(&flow[3 * i0 + 2]);
        float p1x = __ldcs(&pc1[3 * i1 + 0]) + __ldcs(&flow[3 * i1 + 0]);
        float p1y = __ldcs(&pc1[3 * i1 + 1]) + __ldcs(&flow[3 * i1 + 1]);
        float p1z = __ldcs(&pc1[3 * i1 + 2]) + __ldcs(&flow[3 * i1 + 2]);

        Corner a = setup(p0x, p0y, p0z, gx, gy, gz, gf);
        Corner b = setup(p1x, p1y, p1z, gx, gy, gz, gf);

        // Issue all 16 gathers before any dependent math (MLP=16/thread).
        float a000 = __ldg(&grid[a.b00 + a.z0]);
        float a001 = __ldg(&grid[a.b00 + a.z1]);
        float a010 = __ldg(&grid[a.b01 + a.z0]);
        float a011 = __ldg(&grid[a.b01 + a.z1]);
        float a100 = __ldg(&grid[a.b10 + a.z0]);
        float a101 = __ldg(&grid[a.b10 + a.z1]);
        float a110 = __ldg(&grid[a.b11 + a.z0]);
        float a111 = __ldg(&grid[a.b11 + a.z1]);
        float b000 = __ldg(&grid[b.b00 + b.z0]);
        float b001 = __ldg(&grid[b.b00 + b.z1]);
        float b010 = __ldg(&grid[b.b01 + b.z0]);
        float b011 = __ldg(&grid[b.b01 + b.z1]);
        float b100 = __ldg(&grid[b.b10 + b.z0]);
        float b101 = __ldg(&grid[b.b10 + b.z1]);
        float b110 = __ldg(&grid[b.b11 + b.z0]);
        float b111 = __ldg(&grid[b.b11 + b.z1]);

        float v0 = lerp8(a000, a001, a010, a011, a100, a101, a110, a111, a.wx, a.wy, a.wz);
        float v1 = lerp8(b000, b001, b010, b011, b100, b101, b110, b111, b.wx, b.wy, b.wz);

        __stcs(&out[off + i0], v0);
        __stcs(&out[off + i1], v1);
        acc = v0 + v1;
    } else {
        // Tail: handle whichever of i0/i1 is in range, one at a time.
        for (int pass = 0; pass < 2; pass++) {
            int i = pass == 0 ? i0 : i1;
            if (i >= N) continue;
            float px = __ldcs(&pc1[3 * i + 0]) + __ldcs(&flow[3 * i + 0]);
            float py = __ldcs(&pc1[3 * i + 1]) + __ldcs(&flow[3 * i + 1]);
            float pz = __ldcs(&pc1[3 * i + 2]) + __ldcs(&flow[3 * i + 2]);
            Corner a = setup(px, py, pz, gx, gy, gz, gf);
            float v = lerp8(__ldg(&grid[a.b00 + a.z0]), __ldg(&grid[a.b00 + a.z1]),
                            __ldg(&grid[a.b01 + a.z0]), __ldg(&grid[a.b01 + a.z1]),
                            __ldg(&grid[a.b10 + a.z0]), __ldg(&grid[a.b10 + a.z1]),
                            __ldg(&grid[a.b11 + a.z0]), __ldg(&grid[a.b11 + a.z1]),
                            a.wx, a.wy, a.wz);
            __stcs(&out[off + i], v);
            acc += v;
        }
    }

    // ---- block reduction + last-block finalize ----
    __shared__ float warp_sums[BLOCK / 32];
    __shared__ bool  is_last;
    int lane = threadIdx.x & 31;
    int wid  = threadIdx.x >> 5;

    #pragma unroll
    for (int d = 16; d > 0; d >>= 1)
        acc += __shfl_down_sync(0xFFFFFFFFu, acc, d);
    if (lane == 0) warp_sums[wid] = acc;
    __syncthreads();

    if (wid == 0) {
        float s = (lane < BLOCK / 32) ? warp_sums[lane] : 0.0f;
        #pragma unroll
        for (int d = 4; d > 0; d >>= 1)
            s += __shfl_down_sync(0xFFFFFFFFu, s, d);
        if (lane == 0) {
            atomicAdd(&g_sum, s);
            __threadfence();
            unsigned prev = atomicAdd(&g_count, 1u);
            is_last = (prev == gridDim.x - 1);
        }
    }
    __syncthreads();

    if (is_last && threadIdx.x == 0) {
        float total = g_sum;
        if (off > 0) out[0] = total / (float)N;
        g_sum = 0.0f;
        g_count = 0u;
    }
}

extern "C" void kernel_launch(void* const* d_in, const int* in_sizes, int n_in,
                              void* d_out, int out_size)
{
    const float* pc1  = (const float*)d_in[0];
    const float* flow = (const float*)d_in[1];
    const float* grid = (const float*)d_in[2];
    const float* gmin = (const float*)d_in[3];
    const void*  gfac = d_in[4];
    float* out = (float*)d_out;

    int N = in_sizes[0] / 3;
    int off = out_size - N;      // 1 if [mean, dist...], 0 if just [dist...]
    if (off < 0) off = 0;

    int blocks = (N + 2 * BLOCK - 1) / (2 * BLOCK);
    int stride = blocks * BLOCK;

    dt_loss_kernel<<<blocks, BLOCK>>>(pc1, flow, grid, gmin, gfac, out, N, off, stride);
}